// round 7
// baseline (speedup 1.0000x reference)
#include <cuda_runtime.h>
#include <cuda_fp16.h>
#include <math.h>

#define NPTS 65536
#define CDIM 256
#define HEADS 16
#define HD 16
#define KWIN 32
#define NWIN 2048
#define LXYZ 40
#define LRGB 32
#define QSF 4.0f
#define CQSF 8.0f
#define QK_SCALE 0.25f

// half-table layout offsets (in halfs). Row layout TRANSPOSED: [row][c][h][8]
#define T_KX 0
#define T_QX 30720
#define T_VX 61440
#define T_KR 92160
#define T_QR 116736
#define T_VR 141312
#define T_TOT 165888

// Scratch (allocation-free rule: device globals)
__device__ float g_qkv[(size_t)NPTS * 768];
__device__ float g_mid[(size_t)NPTS * CDIM];
__device__ __align__(16) __half g_tabh[T_TOT];

// packed f32x2 FMA: c += a * b (lanewise on two fp32 packed in 64-bit regs)
#define FMA2(c, a, b) \
    asm("fma.rn.f32x2 %0, %1, %2, %0;" : "+l"(c) : "l"(a), "l"(b))

// ---------------------------------------------------------------------------
// Convert fp32 tables to fp16 with transposed row layout [row][c][h][8halfs]
// src element i within one table: row=i>>8, h=(i>>4)&15, c=(i>>3)&1, e=i&7
// dst = (row<<8) | (c<<7) | (h<<3) | e
// ---------------------------------------------------------------------------
__global__ void cvt_tabs(const float* __restrict__ kx, const float* __restrict__ qx,
                         const float* __restrict__ vx, const float* __restrict__ kr,
                         const float* __restrict__ qr, const float* __restrict__ vr)
{
    int i = blockIdx.x * 256 + threadIdx.x;
    int dst = (i & ~255) | ((i & 8) << 4) | ((i & 240) >> 1) | (i & 7);
    if (i < 30720) {
        g_tabh[T_KX + dst] = __float2half(kx[i]);
        g_tabh[T_QX + dst] = __float2half(qx[i]);
        g_tabh[T_VX + dst] = __float2half(vx[i]);
    }
    if (i < 24576) {
        g_tabh[T_KR + dst] = __float2half(kr[i]);
        g_tabh[T_QR + dst] = __float2half(qr[i]);
        g_tabh[T_VR + dst] = __float2half(vr[i]);
    }
}

// ---------------------------------------------------------------------------
// SGEMM: C[M,N] = A[M,K] @ W[N,K]^T + bias[N]
// 128x128 tile, BK=8, 256 threads, 8x8 per thread, double-buffered smem,
// packed f32x2 FMA inner loop.
// ---------------------------------------------------------------------------
__global__ __launch_bounds__(256, 2) void sgemm_nt(
    const float* __restrict__ A, const float* __restrict__ Wm,
    const float* __restrict__ bias, float* __restrict__ Cm,
    int M, int N, int Kd)
{
    __shared__ __align__(16) float As[2][8][128];
    __shared__ __align__(16) float Bs[2][8][128];
    const int tid = threadIdx.x;
    const int tx = tid & 15;
    const int ty = tid >> 4;
    const int brow = blockIdx.y * 128;
    const int bcol = blockIdx.x * 128;
    const int lrow = tid >> 1;
    const int lcol = (tid & 1) * 4;

    const float* Ap = A + (size_t)(brow + lrow) * Kd + lcol;
    const float* Wp = Wm + (size_t)(bcol + lrow) * Kd + lcol;

    unsigned long long acc2[8][4];
#pragma unroll
    for (int m = 0; m < 8; m++)
#pragma unroll
        for (int p = 0; p < 4; p++) acc2[m][p] = 0ull;

    {
        float4 av = *(const float4*)Ap;
        float4 wv = *(const float4*)Wp;
        As[0][lcol + 0][lrow] = av.x; As[0][lcol + 1][lrow] = av.y;
        As[0][lcol + 2][lrow] = av.z; As[0][lcol + 3][lrow] = av.w;
        Bs[0][lcol + 0][lrow] = wv.x; Bs[0][lcol + 1][lrow] = wv.y;
        Bs[0][lcol + 2][lrow] = wv.z; Bs[0][lcol + 3][lrow] = wv.w;
    }
    __syncthreads();

    const int nT = Kd / 8;
    for (int n = 0; n < nT; n++) {
        const int b = n & 1;
        float4 av2, wv2;
        const bool more = (n + 1 < nT);
        if (more) {
            av2 = *(const float4*)(Ap + (n + 1) * 8);
            wv2 = *(const float4*)(Wp + (n + 1) * 8);
        }
#pragma unroll
        for (int k = 0; k < 8; k++) {
            const ulonglong2* bp = (const ulonglong2*)&Bs[b][k][tx * 8];
            ulonglong2 b01 = bp[0];
            ulonglong2 b23 = bp[1];
#pragma unroll
            for (int m = 0; m < 8; m++) {
                unsigned int ai = __float_as_uint(As[b][k][ty * 8 + m]);
                unsigned long long aa;
                asm("mov.b64 %0, {%1, %1};" : "=l"(aa) : "r"(ai));
                FMA2(acc2[m][0], aa, b01.x);
                FMA2(acc2[m][1], aa, b01.y);
                FMA2(acc2[m][2], aa, b23.x);
                FMA2(acc2[m][3], aa, b23.y);
            }
        }
        if (more) {
            const int b2 = b ^ 1;
            As[b2][lcol + 0][lrow] = av2.x; As[b2][lcol + 1][lrow] = av2.y;
            As[b2][lcol + 2][lrow] = av2.z; As[b2][lcol + 3][lrow] = av2.w;
            Bs[b2][lcol + 0][lrow] = wv2.x; Bs[b2][lcol + 1][lrow] = wv2.y;
            Bs[b2][lcol + 2][lrow] = wv2.z; Bs[b2][lcol + 3][lrow] = wv2.w;
        }
        __syncthreads();
    }

#pragma unroll
    for (int m = 0; m < 8; m++) {
        int row = brow + ty * 8 + m;
#pragma unroll
        for (int p = 0; p < 4; p += 2) {
            int col = bcol + tx * 8 + p * 2;
            float c0, c1, c2, c3;
            asm("mov.b64 {%0, %1}, %2;" : "=f"(c0), "=f"(c1) : "l"(acc2[m][p]));
            asm("mov.b64 {%0, %1}, %2;" : "=f"(c2), "=f"(c3) : "l"(acc2[m][p + 1]));
            float4 o;
            o.x = c0 + bias[col + 0];
            o.y = c1 + bias[col + 1];
            o.z = c2 + bias[col + 2];
            o.w = c3 + bias[col + 3];
            *(float4*)&Cm[(size_t)row * N + col] = o;
        }
    }
}

// ---------------------------------------------------------------------------
// Windowed attention: fused single-pass, fp16 tables + fp16 K/V smem
// ---------------------------------------------------------------------------
struct H8 { uint4 u; };
__device__ __forceinline__ H8 ldt(const __half* __restrict__ p) {
    H8 r; r.u = *(const uint4*)p; return r;
}
__device__ __forceinline__ __half2 lane(const H8& a, int l) {
    unsigned w = (l == 0) ? a.u.x : (l == 1) ? a.u.y : (l == 2) ? a.u.z : a.u.w;
    return *reinterpret_cast<const __half2*>(&w);
}
__device__ __forceinline__ __half2 sum6(const H8& a0, const H8& a1, const H8& a2,
                                        const H8& a3, const H8& a4, const H8& a5, int l) {
    return __hadd2(__hadd2(__hadd2(lane(a0, l), lane(a1, l)),
                           __hadd2(lane(a2, l), lane(a3, l))),
                   __hadd2(lane(a4, l), lane(a5, l)));
}

// smem layout:
//   skh    [32*256] halfs @ half-off 0      (16 KB)
//   svh    [32*256] halfs @ half-off 8192   (16 KB)
//   scoord [192] floats   @ float-off 8192
//   spt    [32] int       @ float-off 8384
//   sidx2  [1024] uint2   @ float-off 8416  (ends 10464)
#define ATTN_SMEM_FLOATS 10464
#define ATTN_SMEM_BYTES (ATTN_SMEM_FLOATS * 4)

__global__ __launch_bounds__(256, 3) void win_attn(
    const float* __restrict__ n_coords, const int* __restrict__ n2n)
{
    extern __shared__ float smem[];
    __half* skh = (__half*)smem;
    __half* svh = skh + 8192;
    float* scoord = smem + 8192;
    int* spt = (int*)(smem + 8384);
    uint2* sidx2 = (uint2*)(smem + 8416);

    const int tid = threadIdx.x;
    const int w = blockIdx.x;

    if (tid < KWIN) spt[tid] = n2n[w * KWIN + tid];
    __syncthreads();

    if (tid < 192) {
        int i = tid / 6, d = tid % 6;
        float s = (d < 3) ? QSF : CQSF;
        scoord[tid] = n_coords[(size_t)spt[i] * 6 + d] * s;
    }
    // stage K and V as fp16 (coalesced fp32 gmem reads)
    for (int j = 0; j < KWIN; ++j) {
        size_t base = (size_t)spt[j] * 768;
        skh[j * 256 + tid] = __float2half(g_qkv[base + 256 + tid]);
        svh[j * 256 + tid] = __float2half(g_qkv[base + 512 + tid]);
    }
    __syncthreads();

    // packed relative indices per (i,j)
#pragma unroll
    for (int r = 0; r < 4; ++r) {
        int p = r * 256 + tid;
        int i = p >> 5, j = p & 31;
        const float* ci = scoord + i * 6;
        const float* cj = scoord + j * 6;
        int l[6];
#pragma unroll
        for (int d = 0; d < 3; d++) {
            int v = (int)floorf(ci[d] - cj[d]) + LXYZ / 2;
            l[d] = min(max(v, 0), LXYZ - 1);
        }
#pragma unroll
        for (int d = 0; d < 3; d++) {
            int v = (int)floorf(ci[3 + d] - cj[3 + d]) + LRGB / 2;
            l[3 + d] = min(max(v, 0), LRGB - 1);
        }
        unsigned lo = (unsigned)l[0] | ((unsigned)l[1] << 8) |
                      ((unsigned)l[2] << 16) | ((unsigned)l[3] << 24);
        unsigned hi = (unsigned)l[4] | ((unsigned)l[5] << 8);
        sidx2[p] = make_uint2(lo, hi);
    }
    __syncthreads();

    // each thread owns rows (i,h); 512 rows total, 2 per thread
    for (int r = 0; r < 2; ++r) {
        const int row = r * 256 + tid;
        const int i = row >> 4;
        const int h = row & 15;
        const int hb = h * 16;   // K/V smem base (halfs) & q/out base (floats)
        const int h8 = h * 8;    // transposed table base (halfs)
        const int pt = spt[i];

        const __half* tKX = g_tabh + T_KX + h8;
        const __half* tQX = g_tabh + T_QX + h8;
        const __half* tVX = g_tabh + T_VX + h8;
        const __half* tKR = g_tabh + T_KR + h8;
        const __half* tQR = g_tabh + T_QR + h8;
        const __half* tVR = g_tabh + T_VR + h8;

        // q row (scaled): fp32 + half2 copy
        float qf[16];
        __half2 qh[8];
        {
            const float4* qp = (const float4*)(g_qkv + (size_t)pt * 768 + hb);
#pragma unroll
            for (int t = 0; t < 4; t++) {
                float4 v = qp[t];
                qf[t * 4 + 0] = v.x * QK_SCALE; qf[t * 4 + 1] = v.y * QK_SCALE;
                qf[t * 4 + 2] = v.z * QK_SCALE; qf[t * 4 + 3] = v.w * QK_SCALE;
            }
#pragma unroll
            for (int k = 0; k < 8; k++)
                qh[k] = __floats2half2_rn(qf[2 * k], qf[2 * k + 1]);
        }

        // softmax baseline: main dot vs j=0 (shift only; weights unchanged)
        float bshift = 0.f;
        {
            H8 k0a = ldt(skh + hb);
            H8 k0b = ldt(skh + hb + 8);
#pragma unroll
            for (int l = 0; l < 4; l++) {
                float2 fa = __half22float2(lane(k0a, l));
                float2 fb = __half22float2(lane(k0b, l));
                bshift += qf[2 * l] * fa.x + qf[2 * l + 1] * fa.y +
                          qf[8 + 2 * l] * fb.x + qf[9 + 2 * l] * fb.y;
            }
        }

        float ssum = 0.f;
        float of[16];
#pragma unroll
        for (int e = 0; e < 16; e++) of[e] = 0.f;

        // ---- fused single pass over j ----
        for (int j = 0; j < KWIN; ++j) {
            const uint2 pk = sidx2[i * 32 + j];
            const int r0 = (int)(pk.x & 255) << 8;
            const int r1 = (int)(40 + ((pk.x >> 8) & 255)) << 8;
            const int r2 = (int)(80 + ((pk.x >> 16) & 255)) << 8;
            const int r3 = (int)(pk.x >> 24) << 8;
            const int r4 = (int)(32 + (pk.y & 255)) << 8;
            const int r5 = (int)(64 + ((pk.y >> 8) & 255)) << 8;

            // K row (fp16 -> fp32 main dot)
            H8 kka = ldt(skh + j * 256 + hb);
            H8 kkb = ldt(skh + j * 256 + hb + 8);
            float facc = 0.f;
#pragma unroll
            for (int l = 0; l < 4; l++) {
                float2 fa = __half22float2(lane(kka, l));
                float2 fb = __half22float2(lane(kkb, l));
                facc += qf[2 * l] * fa.x + qf[2 * l + 1] * fa.y +
                        qf[8 + 2 * l] * fb.x + qf[9 + 2 * l] * fb.y;
            }

            // half table logit part (two 8-half chunks)
#pragma unroll
            for (int c = 0; c < 2; c++) {
                const int co = c << 7;
                H8 a0 = ldt(tKX + r0 + co), a1 = ldt(tKX + r1 + co),
                   a2 = ldt(tKX + r2 + co), a3 = ldt(tKR + r3 + co),
                   a4 = ldt(tKR + r4 + co), a5 = ldt(tKR + r5 + co);
                H8 b0 = ldt(tQX + r0 + co), b1 = ldt(tQX + r1 + co),
                   b2 = ldt(tQX + r2 + co), b3 = ldt(tQR + r3 + co),
                   b4 = ldt(tQR + r4 + co), b5 = ldt(tQR + r5 + co);
                const H8& kk = c ? kkb : kka;
                __half2 hq = __float2half2_rn(0.f);
                __half2 hk = hq;
#pragma unroll
                for (int l = 0; l < 4; l++) {
                    __half2 qs = sum6(a0, a1, a2, a3, a4, a5, l);
                    __half2 ks = sum6(b0, b1, b2, b3, b4, b5, l);
                    hq = __hfma2(qh[c * 4 + l], qs, hq);
                    hk = __hfma2(lane(kk, l), ks, hk);
                }
                float2 f = __half22float2(__hadd2(hq, hk));
                facc += f.x + f.y;
            }

            const float a = __expf(facc - bshift);
            ssum += a;

            // value side: fp32 accumulate of a*(v + sum6(vtab))
            H8 vva = ldt(svh + j * 256 + hb);
            H8 vvb = ldt(svh + j * 256 + hb + 8);
#pragma unroll
            for (int c = 0; c < 2; c++) {
                const int co = c << 7;
                H8 v0 = ldt(tVX + r0 + co), v1 = ldt(tVX + r1 + co),
                   v2 = ldt(tVX + r2 + co), v3 = ldt(tVR + r3 + co),
                   v4 = ldt(tVR + r4 + co), v5 = ldt(tVR + r5 + co);
                const H8& vv = c ? vvb : vva;
                float* o = of + c * 8;
#pragma unroll
                for (int l = 0; l < 4; l++) {
                    float2 vf = __half22float2(lane(vv, l));
                    float2 tf = __half22float2(sum6(v0, v1, v2, v3, v4, v5, l));
                    o[2 * l + 0] += a * (vf.x + tf.x);
                    o[2 * l + 1] += a * (vf.y + tf.y);
                }
            }
        }

        const float inv = 1.0f / ssum;
        float4* op = (float4*)(g_mid + (size_t)pt * CDIM + hb);
#pragma unroll
        for (int t = 0; t < 4; t++)
            op[t] = make_float4(of[4 * t] * inv, of[4 * t + 1] * inv,
                                of[4 * t + 2] * inv, of[4 * t + 3] * inv);
    }
}

// ---------------------------------------------------------------------------
extern "C" void kernel_launch(void* const* d_in, const int* in_sizes, int n_in,
                              void* d_out, int out_size)
{
    const float* feats    = (const float*)d_in[0];
    const float* n_coords = (const float*)d_in[1];
    const int*   n2n      = (const int*)d_in[2];
    const float* q_xyz    = (const float*)d_in[3];
    const float* k_xyz    = (const float*)d_in[4];
    const float* v_xyz    = (const float*)d_in[5];
    const float* q_rgb    = (const float*)d_in[6];
    const float* k_rgb    = (const float*)d_in[7];
    const float* v_rgb    = (const float*)d_in[8];
    const float* qkv_w    = (const float*)d_in[9];
    const float* qkv_b    = (const float*)d_in[10];
    const float* proj_w   = (const float*)d_in[11];
    const float* proj_b   = (const float*)d_in[12];
    float* out = (float*)d_out;

    float *qkv_p = nullptr, *mid_p = nullptr;
    cudaGetSymbolAddress((void**)&qkv_p, g_qkv);
    cudaGetSymbolAddress((void**)&mid_p, g_mid);

    cudaFuncSetAttribute(win_attn, cudaFuncAttributeMaxDynamicSharedMemorySize,
                         ATTN_SMEM_BYTES);

    // 0) convert tables to fp16 (transposed rows)
    cvt_tabs<<<120, 256>>>(k_xyz, q_xyz, v_xyz, k_rgb, q_rgb, v_rgb);

    // 1) QKV projection: [65536,256] x [768,256]^T
    dim3 g1(768 / 128, NPTS / 128);
    sgemm_nt<<<g1, 256>>>(feats, qkv_w, qkv_b, qkv_p, NPTS, 768, CDIM);

    // 2) windowed attention (fused)
    win_attn<<<NWIN, 256, ATTN_SMEM_BYTES>>>(n_coords, n2n);

    // 3) output projection: [65536,256] x [256,256]^T
    dim3 g2(CDIM / 128, NPTS / 128);
    sgemm_nt<<<g2, 256>>>(mid_p, proj_w, proj_b, out, NPTS, CDIM, CDIM);
}